// round 11
// baseline (speedup 1.0000x reference)
#include <cuda_runtime.h>

// Denoise_17669495455833: batched FISTA QP (2 passes x 100 iters, rows of 512 fp32).
// R10: issue/latency-bound at fixed occ (144 regs -> 12 warps/SM; all memory trades lose).
//  - Ghost-point boundaries: z[-1]=2z0-z1, z[-2]=3z0-2z1 (mirrored right) make the
//    uniform pentadiagonal stencil EXACT at rows 0,1,n-2,n-1. Removes Q1/Q2/Q3 consts
//    (-6 regs) and all in-loop predicated boundary FMAs.
//  - Deferred k-order (2..15, then 1, then 0) so SHFL results (lat ~26) are consumed
//    ~14 updates after issue. (R8 tested this only together with the smem-y regression.)
//  - State fully register-resident: x,y,z packed f32x2 over two independent rows/warp.

typedef unsigned long long u64;
#define FULL_MASK 0xffffffffu

__device__ u64 g_coefs[100];   // packed (coef, coef) per iteration

__device__ __forceinline__ u64 pk2(float lo, float hi) {
    u64 r;
    asm("mov.b64 %0, {%1,%2};" : "=l"(r) : "r"(__float_as_uint(lo)), "r"(__float_as_uint(hi)));
    return r;
}
__device__ __forceinline__ void upk2(u64 v, float& lo, float& hi) {
    unsigned a, b;
    asm("mov.b64 {%0,%1}, %2;" : "=r"(a), "=r"(b) : "l"(v));
    lo = __uint_as_float(a); hi = __uint_as_float(b);
}
__device__ __forceinline__ u64 fma2(u64 a, u64 b, u64 c) {
    u64 d;
    asm("fma.rn.f32x2 %0, %1, %2, %3;" : "=l"(d) : "l"(a), "l"(b), "l"(c));
    return d;
}
__device__ __forceinline__ u64 add2(u64 a, u64 b) {
    u64 d;
    asm("add.rn.f32x2 %0, %1, %2;" : "=l"(d) : "l"(a), "l"(b));
    return d;
}
__device__ __forceinline__ u64 sub2(u64 a, u64 b) {
    u64 d;
    asm("sub.rn.f32x2 %0, %1, %2;" : "=l"(d) : "l"(a), "l"(b));
    return d;
}
__device__ __forceinline__ u64 mul2(u64 a, u64 b) {
    u64 d;
    asm("mul.rn.f32x2 %0, %1, %2;" : "=l"(d) : "l"(a), "l"(b));
    return d;
}
__device__ __forceinline__ u64 rep2(float f) {
    unsigned u = __float_as_uint(f);
    return ((u64)u << 32) | (u64)u;
}

__global__ void coef_setup_kernel() {
    if (threadIdx.x == 0 && blockIdx.x == 0) {
        float t = 1.0f;
        for (int i = 0; i < 100; ++i) {
            float tn = 0.5f * (1.0f + sqrtf(fmaf(4.0f * t, t, 1.0f)));
            float c  = (t - 1.0f) / tn;
            unsigned u = __float_as_uint(c);
            g_coefs[i] = ((u64)u << 32) | (u64)u;
            t = tn;
        }
    }
}

__global__ void __launch_bounds__(64)
denoise_fista8_kernel(const float* __restrict__ in, float* __restrict__ out, int nrows)
{
    const int gw   = (int)((blockIdx.x * blockDim.x + threadIdx.x) >> 5);  // warp = row pair
    const int lane = (int)(threadIdx.x & 31);
    if (gw * 2 + 1 >= nrows) return;

    const float* rA = in + (size_t)(gw * 2)     * 512 + lane * 16;
    const float* rB = in + (size_t)(gw * 2 + 1) * 512 + lane * 16;

    u64 y[16], x[16], z[16];
    #pragma unroll
    for (int i = 0; i < 16; i += 4) {
        float4 a4 = *reinterpret_cast<const float4*>(rA + i);
        float4 b4 = *reinterpret_cast<const float4*>(rB + i);
        y[i + 0] = pk2(a4.x, b4.x);
        y[i + 1] = pk2(a4.y, b4.y);
        y[i + 2] = pk2(a4.z, b4.z);
        y[i + 3] = pk2(a4.w, b4.w);
    }

    // LAM = 10, step = 1/322.
    // v = z + CZY*(z-y) + CDT*DtD(z),  CZY = -2/322, CDT = -20/322. Precombined:
    const float STEPf = 1.0f / 322.0f;
    const float CZYf  = -2.0f * STEPf;
    const float CDTf  = -2.0f * 10.0f * STEPf;
    const u64 CA = rep2(1.0f + CZYf + 6.0f * CDTf);   // z_j
    const u64 CB = rep2(-4.0f * CDTf);                // z_{j+-1}
    const u64 CC = rep2(CDTf);                        // z_{j+-2}
    const u64 CE = rep2(-CZYf);                       // y_j

    const bool first = (lane == 0);
    const bool last  = (lane == 31);

    #pragma unroll 1
    for (int pass = 0; pass < 2; ++pass) {
        #pragma unroll
        for (int k = 0; k < 16; ++k) { x[k] = y[k]; z[k] = y[k]; }   // x0 = proj(y) = y

        #pragma unroll 1
        for (int it = 0; it < 100; ++it) {
            const u64 coefP = g_coefs[it];

            // neighbor pairs from the previous iterate
            u64 zm2 = __shfl_up_sync  (FULL_MASK, z[14], 1);
            u64 zm1 = __shfl_up_sync  (FULL_MASK, z[15], 1);
            u64 zp1 = __shfl_down_sync(FULL_MASK, z[0],  1);
            u64 zp2 = __shfl_down_sync(FULL_MASK, z[1],  1);

            // ghost points make the uniform stencil exact at the 4 boundary rows:
            //   z[-1] = 2 z0 - z1,  z[-2] = 3 z0 - 2 z1  (and mirrored on the right)
            {
                u64 gm1 = sub2(add2(z[0], z[0]), z[1]);       // 2 z0 - z1
                u64 gm2 = add2(gm1, sub2(z[0], z[1]));        // 3 z0 - 2 z1
                u64 gp1 = sub2(add2(z[15], z[15]), z[14]);    // 2 z511 - z510
                u64 gp2 = add2(gp1, sub2(z[15], z[14]));      // 3 z511 - 2 z510
                if (first) { zm1 = gm1; zm2 = gm2; }
                if (last)  { zp1 = gp1; zp2 = gp2; }
            }

            // saved old values needed by the deferred k=1, k=0 updates
            const u64 oz0 = z[0], oz1 = z[1], oz2 = z[2], oz3 = z[3];

            // ---- main sweep k = 2..15 (shuffle/ghost results consumed only at k>=14) ----
            u64 p2 = oz0, p1 = oz1;   // rotating window of OLD z[k-2], z[k-1]
            #pragma unroll
            for (int k = 2; k < 16; ++k) {
                u64 zc  = z[k];
                u64 zR1 = (k <= 14) ? z[k + 1] : zp1;
                u64 zR2 = (k <= 13) ? z[k + 2] : ((k == 14) ? zp1 : zp2);
                u64 yk  = y[k];

                u64 s1 = add2(p1, zR1);
                u64 s2 = add2(p2, zR2);
                u64 v  = mul2(yk, CE);
                v = fma2(zc, CA, v);
                v = fma2(s1, CB, v);
                v = fma2(s2, CC, v);

                float vlo, vhi, ylo, yhi;
                upk2(v, vlo, vhi);
                upk2(yk, ylo, yhi);
                u64 xn = pk2(fminf(fmaxf(vlo, 0.0f), ylo),
                             fminf(fmaxf(vhi, 0.0f), yhi));

                u64 dx = sub2(xn, x[k]);
                z[k] = fma2(dx, coefP, xn);
                x[k] = xn;

                p2 = p1; p1 = zc;
            }

            // ---- k = 1 (old z[0] intact; right neighbors from saved oz2, oz3) ----
            {
                u64 s1 = add2(oz0, oz2);
                u64 s2 = add2(zm1, oz3);
                u64 v  = mul2(y[1], CE);
                v = fma2(oz1, CA, v);
                v = fma2(s1, CB, v);
                v = fma2(s2, CC, v);

                float vlo, vhi, ylo, yhi;
                upk2(v, vlo, vhi);
                upk2(y[1], ylo, yhi);
                u64 xn = pk2(fminf(fmaxf(vlo, 0.0f), ylo),
                             fminf(fmaxf(vhi, 0.0f), yhi));
                u64 dx = sub2(xn, x[1]);
                z[1] = fma2(dx, coefP, xn);
                x[1] = xn;
            }

            // ---- k = 0 (right neighbors from saved oz1, oz2) ----
            {
                u64 s1 = add2(zm1, oz1);
                u64 s2 = add2(zm2, oz2);
                u64 v  = mul2(y[0], CE);
                v = fma2(oz0, CA, v);
                v = fma2(s1, CB, v);
                v = fma2(s2, CC, v);

                float vlo, vhi, ylo, yhi;
                upk2(v, vlo, vhi);
                upk2(y[0], ylo, yhi);
                u64 xn = pk2(fminf(fmaxf(vlo, 0.0f), ylo),
                             fminf(fmaxf(vhi, 0.0f), yhi));
                u64 dx = sub2(xn, x[0]);
                z[0] = fma2(dx, coefP, xn);
                x[0] = xn;
            }
        }

        if (pass == 0) {
            #pragma unroll
            for (int k = 0; k < 16; ++k) { y[k] = x[k]; z[k] = x[k]; }  // pass 2: y = pass-1 x
        }
    }

    float* oA = out + (size_t)(gw * 2)     * 512 + lane * 16;
    float* oB = out + (size_t)(gw * 2 + 1) * 512 + lane * 16;
    #pragma unroll
    for (int i = 0; i < 16; i += 4) {
        float4 a4, b4;
        upk2(x[i + 0], a4.x, b4.x);
        upk2(x[i + 1], a4.y, b4.y);
        upk2(x[i + 2], a4.z, b4.z);
        upk2(x[i + 3], a4.w, b4.w);
        *reinterpret_cast<float4*>(oA + i) = a4;
        *reinterpret_cast<float4*>(oB + i) = b4;
    }
}

extern "C" void kernel_launch(void* const* d_in, const int* in_sizes, int n_in,
                              void* d_out, int out_size)
{
    const float* in  = (const float*)d_in[0];
    float*       out = (float*)d_out;
    const int nrows  = in_sizes[0] / 512;            // 16384 rows
    coef_setup_kernel<<<1, 32>>>();
    const int warps  = nrows / 2;                    // 2 rows per warp
    const int blocks = (warps + 1) / 2;              // 2 warps per 64-thread block
    denoise_fista8_kernel<<<blocks, 64>>>(in, out, nrows);
}

// round 14
// speedup vs baseline: 1.0449x; 1.0449x over previous
#include <cuda_runtime.h>

// Denoise_17669495455833: batched FISTA QP (2 passes x 100 iters, rows of 512 fp32).
// R13: the ~590us plateau = divergence overhead. ptxas compiles C++ if{} to
// BSSY/BSYNC (never 0-BSSY predication); the 4 lane-divergent boundary-correction
// ifs per warp-iteration cost ~150-220 cyc vs a ~320-cyc compute body.
// Fix: LANE-MASKED constants (Q1F = first?Q1:0, ... via SEL, hoisted pre-loop) and
// UNCONDITIONAL correction FMAs at k in {0,1,14,15} -- lanes 1..30 add zero.
// Body otherwise identical to the R9 champion (packed f32x2, in-order sweep,
// rotating old-z window, scalar FMNMX clip). Iterations stay at 100 (R12: truncation dead).

typedef unsigned long long u64;
#define FULL_MASK 0xffffffffu

__device__ u64 g_coefs[100];   // packed (coef, coef) per iteration

__device__ __forceinline__ u64 pk2(float lo, float hi) {
    u64 r;
    asm("mov.b64 %0, {%1,%2};" : "=l"(r) : "r"(__float_as_uint(lo)), "r"(__float_as_uint(hi)));
    return r;
}
__device__ __forceinline__ void upk2(u64 v, float& lo, float& hi) {
    unsigned a, b;
    asm("mov.b64 {%0,%1}, %2;" : "=r"(a), "=r"(b) : "l"(v));
    lo = __uint_as_float(a); hi = __uint_as_float(b);
}
__device__ __forceinline__ u64 fma2(u64 a, u64 b, u64 c) {
    u64 d;
    asm("fma.rn.f32x2 %0, %1, %2, %3;" : "=l"(d) : "l"(a), "l"(b), "l"(c));
    return d;
}
__device__ __forceinline__ u64 add2(u64 a, u64 b) {
    u64 d;
    asm("add.rn.f32x2 %0, %1, %2;" : "=l"(d) : "l"(a), "l"(b));
    return d;
}
__device__ __forceinline__ u64 sub2(u64 a, u64 b) {
    u64 d;
    asm("sub.rn.f32x2 %0, %1, %2;" : "=l"(d) : "l"(a), "l"(b));
    return d;
}
__device__ __forceinline__ u64 mul2(u64 a, u64 b) {
    u64 d;
    asm("mul.rn.f32x2 %0, %1, %2;" : "=l"(d) : "l"(a), "l"(b));
    return d;
}
__device__ __forceinline__ u64 rep2(float f) {
    unsigned u = __float_as_uint(f);
    return ((u64)u << 32) | (u64)u;
}

__global__ void coef_setup_kernel() {
    if (threadIdx.x == 0 && blockIdx.x == 0) {
        float t = 1.0f;
        for (int i = 0; i < 100; ++i) {
            float tn = 0.5f * (1.0f + sqrtf(fmaf(4.0f * t, t, 1.0f)));
            float c  = (t - 1.0f) / tn;
            unsigned u = __float_as_uint(c);
            g_coefs[i] = ((u64)u << 32) | (u64)u;
            t = tn;
        }
    }
}

__global__ void __launch_bounds__(64)
denoise_fista11_kernel(const float* __restrict__ in, float* __restrict__ out, int nrows)
{
    const int gw   = (int)((blockIdx.x * blockDim.x + threadIdx.x) >> 5);  // warp = row pair
    const int lane = (int)(threadIdx.x & 31);
    if (gw * 2 + 1 >= nrows) return;

    const float* rA = in + (size_t)(gw * 2)     * 512 + lane * 16;
    const float* rB = in + (size_t)(gw * 2 + 1) * 512 + lane * 16;

    u64 y[16], x[16], z[16];
    #pragma unroll
    for (int i = 0; i < 16; i += 4) {
        float4 a4 = *reinterpret_cast<const float4*>(rA + i);
        float4 b4 = *reinterpret_cast<const float4*>(rB + i);
        y[i + 0] = pk2(a4.x, b4.x);
        y[i + 1] = pk2(a4.y, b4.y);
        y[i + 2] = pk2(a4.z, b4.z);
        y[i + 3] = pk2(a4.w, b4.w);
    }

    // LAM = 10, step = 1/322.
    // v = z + CZY*(z-y) + CDT*DtD(z),  CZY = -2/322, CDT = -20/322. Precombined:
    const float STEPf = 1.0f / 322.0f;
    const float CZYf  = -2.0f * STEPf;
    const float CDTf  = -2.0f * 10.0f * STEPf;
    const u64 CA = rep2(1.0f + CZYf + 6.0f * CDTf);   // z_j
    const u64 CB = rep2(-4.0f * CDTf);                // z_{j+-1}
    const u64 CC = rep2(CDTf);                        // z_{j+-2}
    const u64 CE = rep2(-CZYf);                       // y_j

    const bool first = (lane == 0);
    const bool last  = (lane == 31);

    // LANE-MASKED boundary-correction constants (SEL once, no branches in hot loop).
    // True DtD rows minus zero-padded interior stencil, times CDT:
    const u64 Q1F = first ? rep2(-5.0f * CDTf) : 0ULL;
    const u64 Q2F = first ? rep2( 2.0f * CDTf) : 0ULL;
    const u64 Q3F = first ? rep2(-1.0f * CDTf) : 0ULL;
    const u64 Q1L = last  ? rep2(-5.0f * CDTf) : 0ULL;
    const u64 Q2L = last  ? rep2( 2.0f * CDTf) : 0ULL;
    const u64 Q3L = last  ? rep2(-1.0f * CDTf) : 0ULL;

    #pragma unroll 1
    for (int pass = 0; pass < 2; ++pass) {
        #pragma unroll
        for (int k = 0; k < 16; ++k) { x[k] = y[k]; z[k] = y[k]; }   // x0 = proj(y) = y

        #pragma unroll 1
        for (int it = 0; it < 100; ++it) {
            // neighbor pairs (previous iterate); out-of-range -> 0 via SEL (no branch)
            u64 zm2 = __shfl_up_sync  (FULL_MASK, z[14], 1);
            u64 zm1 = __shfl_up_sync  (FULL_MASK, z[15], 1);
            u64 zp1 = __shfl_down_sync(FULL_MASK, z[0],  1);
            u64 zp2 = __shfl_down_sync(FULL_MASK, z[1],  1);
            zm2 = first ? 0ULL : zm2;
            zm1 = first ? 0ULL : zm1;
            zp1 = last  ? 0ULL : zp1;
            zp2 = last  ? 0ULL : zp2;

            const u64 coefP = g_coefs[it];

            // rotating window of OLD z values (z[] is overwritten in place)
            u64 p2 = zm2, p1 = zm1;

            #pragma unroll
            for (int k = 0; k < 16; ++k) {
                u64 zc  = z[k];                                 // old z_j
                u64 zR1 = (k <= 14) ? z[k + 1] : zp1;           // old z_{j+1}
                u64 zR2 = (k <= 13) ? z[k + 2] : ((k == 14) ? zp1 : zp2);  // old z_{j+2}

                u64 s1 = add2(p1, zR1);
                u64 s2 = add2(p2, zR2);
                u64 v  = mul2(y[k], CE);
                v = fma2(zc, CA, v);
                v = fma2(s1, CB, v);
                v = fma2(s2, CC, v);

                // boundary corrections: UNCONDITIONAL, lane-masked constants
                // (zero for interior lanes -> adds 0; no BSSY/BSYNC divergence)
                if (k == 0)  { v = fma2(zc, Q1F, v); v = fma2(z[1],  Q2F, v); }
                if (k == 1)  { v = fma2(p1, Q2F, v); v = fma2(zc,   Q3F, v); }
                if (k == 14) { v = fma2(zc, Q3L, v); v = fma2(z[15], Q2L, v); }
                if (k == 15) { v = fma2(p1, Q2L, v); v = fma2(zc,   Q1L, v); }

                // x_new = clip(v, 0, y)  (scalar FMNMX -> alu pipe)
                float vlo, vhi, ylo, yhi;
                upk2(v, vlo, vhi);
                upk2(y[k], ylo, yhi);
                u64 xn = pk2(fminf(fmaxf(vlo, 0.0f), ylo),
                             fminf(fmaxf(vhi, 0.0f), yhi));

                // z_new = x_new + coef*(x_new - x)
                u64 dx = sub2(xn, x[k]);
                z[k] = fma2(dx, coefP, xn);
                x[k] = xn;

                p2 = p1; p1 = zc;
            }
        }

        if (pass == 0) {
            #pragma unroll
            for (int k = 0; k < 16; ++k) y[k] = x[k];   // pass 2: y = pass-1 output
        }
    }

    float* oA = out + (size_t)(gw * 2)     * 512 + lane * 16;
    float* oB = out + (size_t)(gw * 2 + 1) * 512 + lane * 16;
    #pragma unroll
    for (int i = 0; i < 16; i += 4) {
        float4 a4, b4;
        upk2(x[i + 0], a4.x, b4.x);
        upk2(x[i + 1], a4.y, b4.y);
        upk2(x[i + 2], a4.z, b4.z);
        upk2(x[i + 3], a4.w, b4.w);
        *reinterpret_cast<float4*>(oA + i) = a4;
        *reinterpret_cast<float4*>(oB + i) = b4;
    }
}

extern "C" void kernel_launch(void* const* d_in, const int* in_sizes, int n_in,
                              void* d_out, int out_size)
{
    const float* in  = (const float*)d_in[0];
    float*       out = (float*)d_out;
    const int nrows  = in_sizes[0] / 512;            // 16384 rows
    coef_setup_kernel<<<1, 32>>>();
    const int warps  = nrows / 2;                    // 2 rows per warp
    const int blocks = (warps + 1) / 2;              // 2 warps per 64-thread block
    denoise_fista11_kernel<<<blocks, 64>>>(in, out, nrows);
}

// round 15
// speedup vs baseline: 1.1341x; 1.0853x over previous
#include <cuda_runtime.h>

// Denoise_17669495455833: batched FISTA QP (2 passes x 100 iters, rows of 512 fp32).
// R14: fma-pipe op count IS the runtime (measured fma-busy == op-count model).
// Cut packed fma-pipe ops 136 -> 114 per warp-iteration:
//  (a) hoist w[k] = CE*y[k] out of the iteration loop (y constant per pass): -16 mul2/iter
//  (b) fold 6 of 8 boundary-correction FMAs into per-lane per-k constants
//      (CA_eff/CB_eff absorb Q1/Q2 at k=0,15 where the masked shuffle makes s1
//       single-termed); only k=1,14 keep one extra fma2 each.
// Body otherwise = R13 champion (packed f32x2, lane-masked branchless boundaries,
// rotating old-z window, scalar FMNMX clip).

typedef unsigned long long u64;
#define FULL_MASK 0xffffffffu

__device__ u64 g_coefs[100];   // packed (coef, coef) per iteration

__device__ __forceinline__ u64 pk2(float lo, float hi) {
    u64 r;
    asm("mov.b64 %0, {%1,%2};" : "=l"(r) : "r"(__float_as_uint(lo)), "r"(__float_as_uint(hi)));
    return r;
}
__device__ __forceinline__ void upk2(u64 v, float& lo, float& hi) {
    unsigned a, b;
    asm("mov.b64 {%0,%1}, %2;" : "=r"(a), "=r"(b) : "l"(v));
    lo = __uint_as_float(a); hi = __uint_as_float(b);
}
__device__ __forceinline__ u64 fma2(u64 a, u64 b, u64 c) {
    u64 d;
    asm("fma.rn.f32x2 %0, %1, %2, %3;" : "=l"(d) : "l"(a), "l"(b), "l"(c));
    return d;
}
__device__ __forceinline__ u64 add2(u64 a, u64 b) {
    u64 d;
    asm("add.rn.f32x2 %0, %1, %2;" : "=l"(d) : "l"(a), "l"(b));
    return d;
}
__device__ __forceinline__ u64 sub2(u64 a, u64 b) {
    u64 d;
    asm("sub.rn.f32x2 %0, %1, %2;" : "=l"(d) : "l"(a), "l"(b));
    return d;
}
__device__ __forceinline__ u64 mul2(u64 a, u64 b) {
    u64 d;
    asm("mul.rn.f32x2 %0, %1, %2;" : "=l"(d) : "l"(a), "l"(b));
    return d;
}
__device__ __forceinline__ u64 rep2(float f) {
    unsigned u = __float_as_uint(f);
    return ((u64)u << 32) | (u64)u;
}

__global__ void coef_setup_kernel() {
    if (threadIdx.x == 0 && blockIdx.x == 0) {
        float t = 1.0f;
        for (int i = 0; i < 100; ++i) {
            float tn = 0.5f * (1.0f + sqrtf(fmaf(4.0f * t, t, 1.0f)));
            float c  = (t - 1.0f) / tn;
            unsigned u = __float_as_uint(c);
            g_coefs[i] = ((u64)u << 32) | (u64)u;
            t = tn;
        }
    }
}

__global__ void __launch_bounds__(64)
denoise_fista12_kernel(const float* __restrict__ in, float* __restrict__ out, int nrows)
{
    const int gw   = (int)((blockIdx.x * blockDim.x + threadIdx.x) >> 5);  // warp = row pair
    const int lane = (int)(threadIdx.x & 31);
    if (gw * 2 + 1 >= nrows) return;

    const float* rA = in + (size_t)(gw * 2)     * 512 + lane * 16;
    const float* rB = in + (size_t)(gw * 2 + 1) * 512 + lane * 16;

    u64 y[16], w[16], x[16], z[16];
    #pragma unroll
    for (int i = 0; i < 16; i += 4) {
        float4 a4 = *reinterpret_cast<const float4*>(rA + i);
        float4 b4 = *reinterpret_cast<const float4*>(rB + i);
        y[i + 0] = pk2(a4.x, b4.x);
        y[i + 1] = pk2(a4.y, b4.y);
        y[i + 2] = pk2(a4.z, b4.z);
        y[i + 3] = pk2(a4.w, b4.w);
    }

    // LAM = 10, step = 1/322.
    // v = z + CZY*(z-y) + CDT*DtD(z),  CZY = -2/322, CDT = -20/322. Precombined:
    const float STEPf = 1.0f / 322.0f;
    const float CZYf  = -2.0f * STEPf;
    const float CDTf  = -2.0f * 10.0f * STEPf;
    const float CAf   = 1.0f + CZYf + 6.0f * CDTf;    // z_j
    const float CBf   = -4.0f * CDTf;                 // z_{j+-1}

    const bool first = (lane == 0);
    const bool last  = (lane == 31);

    // boundary corrections folded into per-lane, per-k effective constants.
    // True DtD row deltas (x CDT): row0/rowN-1: -5*CDT on z_j, +2*CDT on inner nbr;
    // row1/rowN-2: -1*CDT on z_j, +2*CDT on outer nbr.
    const float q1 = -5.0f * CDTf, q2 = 2.0f * CDTf, q3 = -1.0f * CDTf;
    const u64 CA    = rep2(CAf);
    const u64 CAk0  = rep2(CAf + (first ? q1 : 0.0f));
    const u64 CAk1  = rep2(CAf + (first ? q3 : 0.0f));
    const u64 CAk14 = rep2(CAf + (last  ? q3 : 0.0f));
    const u64 CAk15 = rep2(CAf + (last  ? q1 : 0.0f));
    const u64 CB    = rep2(CBf);
    const u64 CBk0  = rep2(CBf + (first ? q2 : 0.0f));   // s1 = zR1 only (p1 masked 0)
    const u64 CBk15 = rep2(CBf + (last  ? q2 : 0.0f));   // s1 = p1 only (zR1 masked 0)
    const u64 CC    = rep2(CDTf);                        // z_{j+-2}
    const u64 Q2F   = first ? rep2(q2) : 0ULL;           // extra fma at k=1 (on p1=old z0)
    const u64 Q2L   = last  ? rep2(q2) : 0ULL;           // extra fma at k=14 (on old z15)
    const u64 CE    = rep2(-CZYf);                       // y_j (hoisted: w = CE*y per pass)

    #pragma unroll 1
    for (int pass = 0; pass < 2; ++pass) {
        #pragma unroll
        for (int k = 0; k < 16; ++k) {
            x[k] = y[k]; z[k] = y[k];          // x0 = proj(y) = y
            w[k] = mul2(y[k], CE);             // hoisted data term (constant per pass)
        }

        #pragma unroll 1
        for (int it = 0; it < 100; ++it) {
            const u64 coefP = g_coefs[it];

            // neighbor pairs (previous iterate); out-of-range -> 0 via SEL (no branch)
            u64 zm2 = __shfl_up_sync  (FULL_MASK, z[14], 1);
            u64 zm1 = __shfl_up_sync  (FULL_MASK, z[15], 1);
            u64 zp1 = __shfl_down_sync(FULL_MASK, z[0],  1);
            u64 zp2 = __shfl_down_sync(FULL_MASK, z[1],  1);
            zm2 = first ? 0ULL : zm2;
            zm1 = first ? 0ULL : zm1;
            zp1 = last  ? 0ULL : zp1;
            zp2 = last  ? 0ULL : zp2;

            // rotating window of OLD z values (z[] is overwritten in place)
            u64 p2 = zm2, p1 = zm1;

            #pragma unroll
            for (int k = 0; k < 16; ++k) {
                u64 zc  = z[k];                                 // old z_j
                u64 zR1 = (k <= 14) ? z[k + 1] : zp1;           // old z_{j+1}
                u64 zR2 = (k <= 13) ? z[k + 2] : ((k == 14) ? zp1 : zp2);  // old z_{j+2}

                const u64 CAk = (k == 0) ? CAk0 : (k == 1) ? CAk1
                              : (k == 14) ? CAk14 : (k == 15) ? CAk15 : CA;
                const u64 CBk = (k == 0) ? CBk0 : (k == 15) ? CBk15 : CB;

                u64 s1 = add2(p1, zR1);
                u64 s2 = add2(p2, zR2);
                u64 v  = fma2(zc, CAk, w[k]);
                v = fma2(s1, CBk, v);
                v = fma2(s2, CC, v);
                if (k == 1)  v = fma2(p1,  Q2F, v);   // unconditional, lane-masked const
                if (k == 14) v = fma2(zR1, Q2L, v);   // zR1 here = old z[15]

                // x_new = clip(v, 0, y)  (scalar FMNMX -> alu pipe)
                float vlo, vhi, ylo, yhi;
                upk2(v, vlo, vhi);
                upk2(y[k], ylo, yhi);
                u64 xn = pk2(fminf(fmaxf(vlo, 0.0f), ylo),
                             fminf(fmaxf(vhi, 0.0f), yhi));

                // z_new = x_new + coef*(x_new - x)
                u64 dx = sub2(xn, x[k]);
                z[k] = fma2(dx, coefP, xn);
                x[k] = xn;

                p2 = p1; p1 = zc;
            }
        }

        if (pass == 0) {
            #pragma unroll
            for (int k = 0; k < 16; ++k) y[k] = x[k];   // pass 2: y = pass-1 output
        }
    }

    float* oA = out + (size_t)(gw * 2)     * 512 + lane * 16;
    float* oB = out + (size_t)(gw * 2 + 1) * 512 + lane * 16;
    #pragma unroll
    for (int i = 0; i < 16; i += 4) {
        float4 a4, b4;
        upk2(x[i + 0], a4.x, b4.x);
        upk2(x[i + 1], a4.y, b4.y);
        upk2(x[i + 2], a4.z, b4.z);
        upk2(x[i + 3], a4.w, b4.w);
        *reinterpret_cast<float4*>(oA + i) = a4;
        *reinterpret_cast<float4*>(oB + i) = b4;
    }
}

extern "C" void kernel_launch(void* const* d_in, const int* in_sizes, int n_in,
                              void* d_out, int out_size)
{
    const float* in  = (const float*)d_in[0];
    float*       out = (float*)d_out;
    const int nrows  = in_sizes[0] / 512;            // 16384 rows
    coef_setup_kernel<<<1, 32>>>();
    const int warps  = nrows / 2;                    // 2 rows per warp
    const int blocks = (warps + 1) / 2;              // 2 warps per 64-thread block
    denoise_fista12_kernel<<<blocks, 64>>>(in, out, nrows);
}